// round 5
// baseline (speedup 1.0000x reference)
#include <cuda_runtime.h>
#include <math.h>

#define BB 32
#define NN 96
#define FF 128
#define RPB 8
#define NBLK (BB*(NN/RPB))      // 384
#define THREADS 512
#define LN2f   0.69314718055994530942f
#define LOG2Ef 1.44269504088896340736f
#define PI_5   0.62831853071795864769f

// ---- float offsets into dynamic shared (16640 floats = 66560 B) ----
// region0 (9216 floats): sim tile, dead after hop2; overlaid by:
#define OFF_SIM   0
#define OFF_PACK  0      // compacted float4[8][96] -> 3072 floats
#define OFF_SPART 3072   // accS partials [3][8][128] -> 3072 floats
#define OFF_SA    6144   // A[8][128] -> 1024 floats
#define OFF_SX    9216   // x rows / t2 rows [8][128]
#define OFF_SW    10240  // weight chunk 32*128
#define OFF_R0T   14336  // own sim rows transposed [96][8]
#define OFF_R1T   15104
#define OFF_R2T   15872
#define SMEM_BYTES (16640*4)

extern __shared__ float sm[];

// float2 = sIn[row,:] @ Wg[:, c0..c0+1], staging Wg 32 rows at a time.
// 512 threads: row = t>>6 (const per warp -> LDS broadcast), c0=(t&63)*2.
__device__ __forceinline__ float2 gemm_rowcols(const float* __restrict__ Wg,
                                               const float* sIn, float* sW,
                                               int row, int c0, int t) {
    float a0 = 0.f, a1 = 0.f;
    #pragma unroll
    for (int kb = 0; kb < FF; kb += 32) {
        __syncthreads();
        ((float4*)sW)[t]       = ((const float4*)(Wg + kb*FF))[t];
        ((float4*)sW)[t + 512] = ((const float4*)(Wg + kb*FF))[t + 512];
        __syncthreads();
        #pragma unroll 8
        for (int kk = 0; kk < 32; kk++) {
            float  av = sIn[row*FF + kb + kk];
            float2 wv = *(const float2*)&sW[kk*FF + c0];
            a0 = fmaf(av, wv.x, a0);
            a1 = fmaf(av, wv.y, a1);
        }
    }
    return make_float2(a0, a1);
}

__global__ __launch_bounds__(THREADS) void k_fused(
    const float* __restrict__ x,    const float* __restrict__ r,
    const float* __restrict__ mask, const float* __restrict__ Win,
    const float* __restrict__ fw1,  const float* __restrict__ fb1,
    const float* __restrict__ fw2,  const float* __restrict__ fb2,
    const float* __restrict__ Wout, const float* __restrict__ bout,
    float* __restrict__ out)
{
    __shared__ float invn_s[RPB], csum_s[RPB];
    __shared__ int   cnt_s[RPB];

    const int b  = blockIdx.x / (NN/RPB);
    const int i0 = (blockIdx.x % (NN/RPB)) * RPB;
    const int t  = threadIdx.x;
    const size_t bbase = (size_t)b * NN * NN;

    // ---- prefetch x rows into sX (region untouched until GEMM1) ----
    if (t < RPB*FF/4)
        ((float4*)&sm[OFF_SX])[t] = ((const float4*)(x + (size_t)(b*NN + i0)*FF))[t];

    // ---- 1. sim tile: sim[i][j] = exp(-r)*mask  (9216 = 18*512) ----
    #pragma unroll
    for (int ii = 0; ii < 18; ii++) {
        int idx = ii*THREADS + t;
        float rv = r[bbase + idx];
        float m  = mask[bbase + idx];
        sm[OFF_SIM + idx] = __expf(-rv) * m;
    }
    __syncthreads();

    // ---- 2. n_atoms for own rows (warps 0..7); sim==0 <=> mask==0 ----
    {
        int w = t >> 5, lane = t & 31;
        if (w < RPB) {
            int n = 0;
            #pragma unroll
            for (int ch = 0; ch < 3; ch++) {
                bool nz = sm[OFF_SIM + (i0+w)*NN + ch*32 + lane] != 0.0f;
                n += __popc(__ballot_sync(0xffffffffu, nz));
            }
            if (lane == 0) invn_s[w] = 1.0f / fmaxf((float)n, 1.0f);
        }
    }
    // ---- 3. own sim rows transposed ----
    for (int idx = t; idx < RPB*NN; idx += THREADS) {
        int rr = idx / NN, j = idx - rr*NN;
        sm[OFF_R0T + j*RPB + rr] = sm[OFF_SIM + (i0+rr)*NN + j];
    }
    __syncthreads();

    // ---- 4. hop1: 384 threads = 96 cols x 4 rowgroups of 2 ----
    if (t < 4*NN) {
        int rg = t / NN, col = t - rg*NN, rb = rg*2;
        float a0 = 0.f, a1 = 0.f;
        #pragma unroll 8
        for (int j = 0; j < NN; j++) {
            float  sv = sm[OFF_SIM + j*NN + col];
            float2 rv = *(const float2*)&sm[OFF_R0T + j*RPB + rb];
            a0 = fmaf(rv.x, sv, a0);
            a1 = fmaf(rv.y, sv, a1);
        }
        *(float2*)&sm[OFF_R1T + col*RPB + rb] =
            make_float2(a0*invn_s[rb], a1*invn_s[rb+1]);
    }
    __syncthreads();

    // ---- 5. hop2 ----
    if (t < 4*NN) {
        int rg = t / NN, col = t - rg*NN, rb = rg*2;
        float a0 = 0.f, a1 = 0.f;
        #pragma unroll 8
        for (int j = 0; j < NN; j++) {
            float  sv = sm[OFF_SIM + j*NN + col];
            float2 rv = *(const float2*)&sm[OFF_R1T + j*RPB + rb];
            a0 = fmaf(rv.x, sv, a0);
            a1 = fmaf(rv.y, sv, a1);
        }
        *(float2*)&sm[OFF_R2T + col*RPB + rb] =
            make_float2(a0*invn_s[rb], a1*invn_s[rb+1]);
    }
    __syncthreads();   // sim tile dead from here; pack overlays it

    // ---- 6. compaction (warps 0..7), reads r0T not sim ----
    {
        int w = t >> 5, lane = t & 31;
        if (w < RPB) {
            float4* pk = (float4*)&sm[OFF_PACK];
            int cnt = 0; float cs = 0.0f;
            #pragma unroll
            for (int ch = 0; ch < 3; ch++) {
                int   j  = ch*32 + lane;
                float s0 = sm[OFF_R0T + j*RPB + w];
                float rv = r[bbase + (size_t)(i0+w)*NN + j];
                float c  = 0.0f;
                if (rv < 5.0f && s0 != 0.0f)
                    c = 0.5f * (__cosf(rv * PI_5) + 1.0f);
                cs += c;
                bool p = (c != 0.0f);
                unsigned bm = __ballot_sync(0xffffffffu, p);
                int pos = cnt + __popc(bm & ((1u << lane) - 1u));
                if (p)
                    pk[w*NN + pos] = make_float4(s0, sm[OFF_R1T + j*RPB + w],
                                                 sm[OFF_R2T + j*RPB + w], c * LN2f);
                cnt += __popc(bm);
            }
            #pragma unroll
            for (int o = 16; o > 0; o >>= 1) cs += __shfl_down_sync(0xffffffffu, cs, o);
            if (lane == 0) { cnt_s[w] = cnt; csum_s[w] = cs; }
        }
    }
    __syncthreads();

    // ---- 7. accS (log2 domain), j-loop split across 4 quarters ----
    {
        int f = t & (FF-1), h = t >> 7;        // h in 0..3
        float w0 = fw1[f]        * LOG2Ef;
        float w1 = fw1[FF + f]   * LOG2Ef;
        float w2 = fw1[2*FF + f] * LOG2Ef;
        float b1 = fb1[f]        * LOG2Ef;
        const float4* pk = (const float4*)&sm[OFF_PACK];
        float accv[RPB];
        #pragma unroll
        for (int rr = 0; rr < RPB; rr++) {
            int cnt = cnt_s[rr];
            int q   = (cnt + 3) >> 2;
            int jb  = h*q;
            int je  = min(jb + q, cnt);
            float a = 0.0f;
            for (int jj = jb; jj < je; jj++) {
                float4 p  = pk[rr*NN + jj];
                float  tt = fmaf(p.z, w2, fmaf(p.y, w1, fmaf(p.x, w0, b1)));
                float  u;  asm("ex2.approx.f32 %0, %1;" : "=f"(u)  : "f"(-fabsf(tt)));
                float  v  = fmaf(u, 0.5f, 0.5f);
                float  lg; asm("lg2.approx.f32 %0, %1;" : "=f"(lg) : "f"(v));
                a = fmaf(p.w, fmaxf(tt, 0.0f) + lg, a);
            }
            accv[rr] = a;
        }
        if (h) {
            #pragma unroll
            for (int rr = 0; rr < RPB; rr++)
                sm[OFF_SPART + (h-1)*1024 + rr*FF + f] = accv[rr];
        }
        __syncthreads();
        if (h == 0) {
            #pragma unroll
            for (int rr = 0; rr < RPB; rr++)
                sm[OFF_SA + rr*FF + f] = accv[rr]
                    + sm[OFF_SPART +        rr*FF + f]
                    + sm[OFF_SPART + 1024 + rr*FF + f]
                    + sm[OFF_SPART + 2048 + rr*FF + f];
        }
    }
    // (sA visibility ordered by the staging sync inside gemm_rowcols)

    // ---- 8. GEMM chain on own 8 rows (2 cols/thread) ----
    const int row = t >> 6;               // 0..7, constant per warp
    const int c0  = (t & 63) * 2;

    // GEMM1: ypre stays in registers
    float2 yp = gemm_rowcols(Win, &sm[OFF_SX], &sm[OFF_SW], row, c0, t);

    // GEMM2: t2 = (A @ fw2 + fb2*csum) * ypre  -> overwrite sX
    float2 t2 = gemm_rowcols(fw2, &sm[OFF_SA], &sm[OFF_SW], row, c0, t);
    {
        float  cs = csum_s[row];
        float2 fb = *(const float2*)&fb2[c0];
        float2 o;
        o.x = fmaf(fb.x, cs, t2.x) * yp.x;
        o.y = fmaf(fb.y, cs, t2.y) * yp.y;
        *(float2*)&sm[OFF_SX + row*FF + c0] = o;
    }

    // GEMM3: out = ssp(t2 @ Wout + bout)
    float2 t3 = gemm_rowcols(Wout, &sm[OFF_SX], &sm[OFF_SW], row, c0, t);
    {
        float2 bo = *(const float2*)&bout[c0];
        float  vin[2] = { t3.x + bo.x, t3.y + bo.y };
        float2 o; float* op = (float*)&o;
        #pragma unroll
        for (int q = 0; q < 2; q++) {
            float u = vin[q] * LOG2Ef;
            float e;  asm("ex2.approx.f32 %0, %1;" : "=f"(e)  : "f"(-fabsf(u)));
            float v = fmaf(e, 0.5f, 0.5f);
            float lg; asm("lg2.approx.f32 %0, %1;" : "=f"(lg) : "f"(v));
            op[q] = LN2f * (fmaxf(u, 0.0f) + lg);
        }
        *(float2*)&out[(size_t)(b*NN + i0 + row)*FF + c0] = o;
    }
}

// ================= launch =================
extern "C" void kernel_launch(void* const* d_in, const int* in_sizes, int n_in,
                              void* d_out, int out_size) {
    const float* x      = (const float*)d_in[0];
    const float* r      = (const float*)d_in[1];
    // d_in[2] = neighbors (unused by this forward variant)
    const float* mask   = (const float*)d_in[3];
    const float* W_in2f = (const float*)d_in[4];
    const float* fw1    = (const float*)d_in[5];
    const float* fb1    = (const float*)d_in[6];
    const float* fw2    = (const float*)d_in[7];
    const float* fb2    = (const float*)d_in[8];
    const float* W_out  = (const float*)d_in[9];
    const float* b_out  = (const float*)d_in[10];
    float* out = (float*)d_out;

    // Unconditional (no static guard): idempotent, immediate host API,
    // identical behavior on every call including the graph-capture call.
    cudaFuncSetAttribute(k_fused, cudaFuncAttributeMaxDynamicSharedMemorySize, SMEM_BYTES);

    k_fused<<<NBLK, THREADS, SMEM_BYTES>>>(x, r, mask, W_in2f, fw1, fb1, fw2, fb2,
                                           W_out, b_out, out);
}

// round 6
// speedup vs baseline: 1.3662x; 1.3662x over previous
#include <cuda_runtime.h>
#include <math.h>

#define BB 32
#define NN 96
#define FF 128
#define RPB 8
#define NBLK (BB*(NN/RPB))      // 384
#define THREADS 256
#define LN2f   0.69314718055994530942f
#define LOG2Ef 1.44269504088896340736f
#define PI_5   0.62831853071795864769f

// ---- float offsets into dynamic shared (12544 floats = 50176 B) ----
// region0 (9216 floats) = sim tile, dead after hop2; overlaid by:
#define OFF_SIM   0
#define OFF_PACK  0      // compacted float4[8][96] -> 3072 floats (dead after accS)
#define OFF_SPART 3072   // accS partial [8][128]   -> 1024 floats (dead after accS)
#define OFF_SA    4096   // A[8][128]    -> 1024 floats (live accS..GEMM2)
#define OFF_PART  5120   // GEMM k-split partials [4][8][128] -> 4096 floats
#define OFF_SX    9216   // x rows / t2 rows [8][128]
#define OFF_R0T   10240  // own sim rows transposed [96][8]
#define OFF_R1T   11008
#define OFF_R2T   11776
#define SMEM_BYTES (12544*4)

extern __shared__ float sm[];

// ---- K-split GEMM partial: thread (c=t&31, rg=(t>>5)&1, s=t>>6) computes
// acc[4 rows][4 cols] over kk in [32s, 32s+32), weights straight from L2.
__device__ __forceinline__ void gemm_partial(const float* __restrict__ Wg,
                                             const float* sIn, float* part,
                                             int t) {
    const int c  = (t & 31) * 4;
    const int rg = ((t >> 5) & 1) * 4;
    const int s  = (t >> 6) * 32;
    float acc[4][4];
    #pragma unroll
    for (int i = 0; i < 4; i++)
        #pragma unroll
        for (int q = 0; q < 4; q++) acc[i][q] = 0.0f;

    const float4* Wp = (const float4*)(Wg + s * FF + c);
    #pragma unroll 8
    for (int kk = 0; kk < 32; kk++) {
        float4 wv = __ldg(Wp + kk * (FF/4));
        #pragma unroll
        for (int rr = 0; rr < 4; rr++) {
            float av = sIn[(rg + rr) * FF + s + kk];   // warp-uniform -> LDS broadcast
            acc[rr][0] = fmaf(av, wv.x, acc[rr][0]);
            acc[rr][1] = fmaf(av, wv.y, acc[rr][1]);
            acc[rr][2] = fmaf(av, wv.z, acc[rr][2]);
            acc[rr][3] = fmaf(av, wv.w, acc[rr][3]);
        }
    }
    float* pb = part + (t >> 6) * (RPB*FF);
    #pragma unroll
    for (int rr = 0; rr < 4; rr++)
        *(float4*)&pb[(rg + rr) * FF + c] =
            make_float4(acc[rr][0], acc[rr][1], acc[rr][2], acc[rr][3]);
}

// ---- reduce 4 k-split partials for this thread's (orow, oc..oc+3) slot ----
__device__ __forceinline__ float4 gemm_reduce(const float* part, int orow, int oc) {
    float4 p0 = *(const float4*)&part[0*RPB*FF + orow*FF + oc];
    float4 p1 = *(const float4*)&part[1*RPB*FF + orow*FF + oc];
    float4 p2 = *(const float4*)&part[2*RPB*FF + orow*FF + oc];
    float4 p3 = *(const float4*)&part[3*RPB*FF + orow*FF + oc];
    return make_float4((p0.x+p1.x)+(p2.x+p3.x), (p0.y+p1.y)+(p2.y+p3.y),
                       (p0.z+p1.z)+(p2.z+p3.z), (p0.w+p1.w)+(p2.w+p3.w));
}

__global__ __launch_bounds__(THREADS) void k_fused(
    const float* __restrict__ x,    const float* __restrict__ r,
    const float* __restrict__ mask, const float* __restrict__ Win,
    const float* __restrict__ fw1,  const float* __restrict__ fb1,
    const float* __restrict__ fw2,  const float* __restrict__ fb2,
    const float* __restrict__ Wout, const float* __restrict__ bout,
    float* __restrict__ out)
{
    __shared__ float invn_s[RPB], csum_s[RPB];
    __shared__ int   cnt_s[RPB];

    const int b  = blockIdx.x / (NN/RPB);
    const int i0 = (blockIdx.x % (NN/RPB)) * RPB;
    const int t  = threadIdx.x;
    const size_t bbase = (size_t)b * NN * NN;

    // ---- prefetch x rows into sX (region untouched until GEMM1) ----
    ((float4*)&sm[OFF_SX])[t] = ((const float4*)(x + (size_t)(b*NN + i0)*FF))[t];

    // ---- 1. sim tile: sim[i][j] = exp(-r)*mask ----
    #pragma unroll
    for (int ii = 0; ii < NN*NN/THREADS; ii++) {
        int idx = ii*THREADS + t;
        float rv = r[bbase + idx];
        float m  = mask[bbase + idx];
        sm[OFF_SIM + idx] = __expf(-rv) * m;
    }
    __syncthreads();

    // ---- 2. n_atoms for own rows (warp w -> row i0+w); sim==0 <=> mask==0 ----
    {
        int w = t >> 5, lane = t & 31;
        int n = 0;
        #pragma unroll
        for (int ch = 0; ch < 3; ch++) {
            bool nz = sm[OFF_SIM + (i0+w)*NN + ch*32 + lane] != 0.0f;
            n += __popc(__ballot_sync(0xffffffffu, nz));
        }
        if (lane == 0) invn_s[w] = 1.0f / fmaxf((float)n, 1.0f);
    }
    // ---- 3. own sim rows transposed ----
    for (int idx = t; idx < RPB*NN; idx += THREADS) {
        int rr = idx / NN, j = idx - rr*NN;
        sm[OFF_R0T + j*RPB + rr] = sm[OFF_SIM + (i0+rr)*NN + j];
    }
    __syncthreads();

    // ---- 4. hop1: 192 threads = 96 cols x 2 rowgroups of 4 ----
    if (t < 2*NN) {
        int gr = (t >= NN), col = t - NN*gr, rb = gr*4;
        float a0=0.f,a1=0.f,a2=0.f,a3=0.f;
        #pragma unroll 8
        for (int j = 0; j < NN; j++) {
            float  sv = sm[OFF_SIM + j*NN + col];
            float4 rv = *(const float4*)&sm[OFF_R0T + j*RPB + rb];
            a0 = fmaf(rv.x, sv, a0); a1 = fmaf(rv.y, sv, a1);
            a2 = fmaf(rv.z, sv, a2); a3 = fmaf(rv.w, sv, a3);
        }
        *(float4*)&sm[OFF_R1T + col*RPB + rb] =
            make_float4(a0*invn_s[rb], a1*invn_s[rb+1], a2*invn_s[rb+2], a3*invn_s[rb+3]);
    }
    __syncthreads();

    // ---- 5. hop2 ----
    if (t < 2*NN) {
        int gr = (t >= NN), col = t - NN*gr, rb = gr*4;
        float a0=0.f,a1=0.f,a2=0.f,a3=0.f;
        #pragma unroll 8
        for (int j = 0; j < NN; j++) {
            float  sv = sm[OFF_SIM + j*NN + col];
            float4 rv = *(const float4*)&sm[OFF_R1T + j*RPB + rb];
            a0 = fmaf(rv.x, sv, a0); a1 = fmaf(rv.y, sv, a1);
            a2 = fmaf(rv.z, sv, a2); a3 = fmaf(rv.w, sv, a3);
        }
        *(float4*)&sm[OFF_R2T + col*RPB + rb] =
            make_float4(a0*invn_s[rb], a1*invn_s[rb+1], a2*invn_s[rb+2], a3*invn_s[rb+3]);
    }
    __syncthreads();   // sim tile dead from here; pack/part overlay it

    // ---- 6. compaction (warp w -> row i0+w), reads r0T not sim ----
    {
        int w = t >> 5, lane = t & 31;
        float4* pk = (float4*)&sm[OFF_PACK];
        int cnt = 0; float cs = 0.0f;
        #pragma unroll
        for (int ch = 0; ch < 3; ch++) {
            int   j  = ch*32 + lane;
            float s0 = sm[OFF_R0T + j*RPB + w];
            float rv = r[bbase + (size_t)(i0+w)*NN + j];
            float c  = 0.0f;
            if (rv < 5.0f && s0 != 0.0f)
                c = 0.5f * (__cosf(rv * PI_5) + 1.0f);
            cs += c;
            bool p = (c != 0.0f);
            unsigned bm = __ballot_sync(0xffffffffu, p);
            int pos = cnt + __popc(bm & ((1u << lane) - 1u));
            if (p)
                pk[w*NN + pos] = make_float4(s0, sm[OFF_R1T + j*RPB + w],
                                             sm[OFF_R2T + j*RPB + w], c * LN2f);
            cnt += __popc(bm);
        }
        #pragma unroll
        for (int o = 16; o > 0; o >>= 1) cs += __shfl_down_sync(0xffffffffu, cs, o);
        if (lane == 0) { cnt_s[w] = cnt; csum_s[w] = cs; }
    }
    __syncthreads();

    // ---- 7. accS (log2 domain), j-loop split across two halves ----
    {
        int f = t & (FF-1), h = t >> 7;        // h in {0,1}
        float w0 = fw1[f]        * LOG2Ef;
        float w1 = fw1[FF + f]   * LOG2Ef;
        float w2 = fw1[2*FF + f] * LOG2Ef;
        float b1 = fb1[f]        * LOG2Ef;
        const float4* pk = (const float4*)&sm[OFF_PACK];
        float accv[RPB];
        #pragma unroll
        for (int rr = 0; rr < RPB; rr++) {
            int cnt  = cnt_s[rr];
            int half = (cnt + 1) >> 1;
            int jb   = h ? half : 0;
            int je   = h ? cnt  : half;
            float a = 0.0f;
            for (int jj = jb; jj < je; jj++) {
                float4 p  = pk[rr*NN + jj];
                float  tt = fmaf(p.z, w2, fmaf(p.y, w1, fmaf(p.x, w0, b1)));
                float  u;  asm("ex2.approx.f32 %0, %1;" : "=f"(u)  : "f"(-fabsf(tt)));
                float  v  = fmaf(u, 0.5f, 0.5f);
                float  lg; asm("lg2.approx.f32 %0, %1;" : "=f"(lg) : "f"(v));
                a = fmaf(p.w, fmaxf(tt, 0.0f) + lg, a);
            }
            accv[rr] = a;
        }
        if (h) {
            #pragma unroll
            for (int rr = 0; rr < RPB; rr++) sm[OFF_SPART + rr*FF + f] = accv[rr];
        }
        __syncthreads();
        if (!h) {
            #pragma unroll
            for (int rr = 0; rr < RPB; rr++)
                sm[OFF_SA + rr*FF + f] = accv[rr] + sm[OFF_SPART + rr*FF + f];
        }
    }
    __syncthreads();   // SA complete; pack/spart dead; part region free

    // ---- 8. GEMM chain: k-split, weights via LDG, partials in smem ----
    const int orow = t >> 5;          // reducer's row (0..7)
    const int oc   = (t & 31) * 4;    // reducer's 4 cols

    // GEMM1: ypre = x @ Win   (result stays in this thread's registers)
    gemm_partial(Win, &sm[OFF_SX], &sm[OFF_PART], t);
    __syncthreads();
    float4 yp = gemm_reduce(&sm[OFF_PART], orow, oc);
    __syncthreads();                               // part reads done

    // GEMM2: t2 = (A @ fw2 + fb2*csum) * ypre  -> sX (x is dead)
    gemm_partial(fw2, &sm[OFF_SA], &sm[OFF_PART], t);
    __syncthreads();
    {
        float4 t2 = gemm_reduce(&sm[OFF_PART], orow, oc);
        float  cs = csum_s[orow];
        float4 fb = *(const float4*)&fb2[oc];
        float4 o;
        o.x = fmaf(fb.x, cs, t2.x) * yp.x;  o.y = fmaf(fb.y, cs, t2.y) * yp.y;
        o.z = fmaf(fb.z, cs, t2.z) * yp.z;  o.w = fmaf(fb.w, cs, t2.w) * yp.w;
        *(float4*)&sm[OFF_SX + orow*FF + oc] = o;
    }
    __syncthreads();                               // sX writes visible, part reads done

    // GEMM3: out = ssp(t2 @ Wout + bout)
    gemm_partial(Wout, &sm[OFF_SX], &sm[OFF_PART], t);
    __syncthreads();
    {
        float4 t3 = gemm_reduce(&sm[OFF_PART], orow, oc);
        float4 bo = *(const float4*)&bout[oc];
        float  vin[4] = { t3.x + bo.x, t3.y + bo.y, t3.z + bo.z, t3.w + bo.w };
        float4 o; float* op = (float*)&o;
        #pragma unroll
        for (int q = 0; q < 4; q++) {
            float u = vin[q] * LOG2Ef;
            float e;  asm("ex2.approx.f32 %0, %1;" : "=f"(e)  : "f"(-fabsf(u)));
            float v = fmaf(e, 0.5f, 0.5f);
            float lg; asm("lg2.approx.f32 %0, %1;" : "=f"(lg) : "f"(v));
            op[q] = LN2f * (fmaxf(u, 0.0f) + lg);
        }
        *(float4*)&out[(size_t)(b*NN + i0 + orow)*FF + oc] = o;
    }
}

// ================= launch =================
extern "C" void kernel_launch(void* const* d_in, const int* in_sizes, int n_in,
                              void* d_out, int out_size) {
    const float* x      = (const float*)d_in[0];
    const float* r      = (const float*)d_in[1];
    // d_in[2] = neighbors (unused by this forward variant)
    const float* mask   = (const float*)d_in[3];
    const float* W_in2f = (const float*)d_in[4];
    const float* fw1    = (const float*)d_in[5];
    const float* fb1    = (const float*)d_in[6];
    const float* fw2    = (const float*)d_in[7];
    const float* fb2    = (const float*)d_in[8];
    const float* W_out  = (const float*)d_in[9];
    const float* b_out  = (const float*)d_in[10];
    float* out = (float*)d_out;

    // Unconditional (no static guard): idempotent, immediate host API,
    // identical behavior on every call including the graph-capture call.
    cudaFuncSetAttribute(k_fused, cudaFuncAttributeMaxDynamicSharedMemorySize, SMEM_BYTES);

    k_fused<<<NBLK, THREADS, SMEM_BYTES>>>(x, r, mask, W_in2f, fw1, fb1, fw2, fb2,
                                           W_out, b_out, out);
}

// round 8
// speedup vs baseline: 1.5027x; 1.0999x over previous
#include <cuda_runtime.h>
#include <math.h>

#define BB 32
#define NN 96
#define FF 128
#define RPB 4
#define NBLK (BB*(NN/RPB))      // 768
#define THREADS 256
#define LN2f   0.69314718055994530942f
#define LOG2Ef 1.44269504088896340736f
#define PI_5   0.62831853071795864769f

// ---- float offsets into dynamic shared (11264 floats = 45056 B) ----
// region0 (9216 floats) = sim tile, dead after hop2; overlaid by:
#define OFF_SIM   0
#define OFF_PACK  0      // compacted float4[4][96] -> 1536 floats (dead after accS)
#define OFF_SPART 1536   // accS partial [4][128]   -> 512 floats  (dead after accS)
#define OFF_SA    2048   // A[4][128]   -> 512 floats (live accS..GEMM2)
#define OFF_PART  2560   // GEMM k-split partials [8][4][128] -> 4096 floats
#define OFF_SX    9216   // x rows / t2 rows [4][128] -> 512
#define OFF_R0T   9728   // own sim rows transposed [96][4]
#define OFF_R1T   10112
#define OFF_R2T   10496
#define OFF_HOPP  10880  // hop j-split partials [96][4]
#define SMEM_BYTES (11264*4)

extern __shared__ float sm[];

// ---- K-split GEMM partial: thread (c=(t&31)*4, s=t>>5) computes
// acc[4 rows][4 cols] over kk in [16s, 16s+16), weights straight from L2.
__device__ __forceinline__ void gemm_partial(const float* __restrict__ Wg,
                                             const float* sIn, float* part,
                                             int t) {
    const int c = (t & 31) * 4;
    const int s = t >> 5;               // 0..7
    float acc[4][4];
    #pragma unroll
    for (int i = 0; i < 4; i++)
        #pragma unroll
        for (int q = 0; q < 4; q++) acc[i][q] = 0.0f;

    const float4* Wp = (const float4*)(Wg + (s*16) * FF + c);
    #pragma unroll
    for (int kk = 0; kk < 16; kk++) {
        float4 wv = __ldg(Wp + kk * (FF/4));
        #pragma unroll
        for (int rr = 0; rr < 4; rr++) {
            float av = sIn[rr * FF + s*16 + kk];   // warp-uniform -> LDS broadcast
            acc[rr][0] = fmaf(av, wv.x, acc[rr][0]);
            acc[rr][1] = fmaf(av, wv.y, acc[rr][1]);
            acc[rr][2] = fmaf(av, wv.z, acc[rr][2]);
            acc[rr][3] = fmaf(av, wv.w, acc[rr][3]);
        }
    }
    float* pb = part + s * (RPB*FF);
    #pragma unroll
    for (int rr = 0; rr < 4; rr++)
        *(float4*)&pb[rr * FF + c] =
            make_float4(acc[rr][0], acc[rr][1], acc[rr][2], acc[rr][3]);
}

// ---- reduce 8 k-split partials for slot (orow, oc..oc+3); callers are t<128 ----
__device__ __forceinline__ float4 gemm_reduce(const float* part, int orow, int oc) {
    float4 s0 = *(const float4*)&part[0*RPB*FF + orow*FF + oc];
    #pragma unroll
    for (int s = 1; s < 8; s++) {
        float4 p = *(const float4*)&part[s*RPB*FF + orow*FF + oc];
        s0.x += p.x; s0.y += p.y; s0.z += p.z; s0.w += p.w;
    }
    return s0;
}

__global__ __launch_bounds__(THREADS) void k_fused(
    const float* __restrict__ x,    const float* __restrict__ r,
    const float* __restrict__ mask, const float* __restrict__ Win,
    const float* __restrict__ fw1,  const float* __restrict__ fb1,
    const float* __restrict__ fw2,  const float* __restrict__ fb2,
    const float* __restrict__ Wout, const float* __restrict__ bout,
    float* __restrict__ out)
{
    __shared__ float invn_s[RPB], csum_s[RPB];
    __shared__ int   cnt_s[RPB];

    const int b  = blockIdx.x / (NN/RPB);
    const int i0 = (blockIdx.x % (NN/RPB)) * RPB;
    const int t  = threadIdx.x;
    const size_t bbase = (size_t)b * NN * NN;

    // ---- prefetch x rows into sX (region untouched until GEMM1) ----
    if (t < RPB*FF/4)
        ((float4*)&sm[OFF_SX])[t] = ((const float4*)(x + (size_t)(b*NN + i0)*FF))[t];

    // ---- 1. sim tile: sim[i][j] = exp(-r)*mask ----
    #pragma unroll
    for (int ii = 0; ii < NN*NN/THREADS; ii++) {
        int idx = ii*THREADS + t;
        float rv = r[bbase + idx];
        float m  = mask[bbase + idx];
        sm[OFF_SIM + idx] = __expf(-rv) * m;
    }
    __syncthreads();

    // ---- 2. n_atoms (warps 0..3 -> rows i0..i0+3); sim==0 <=> mask==0 ----
    {
        int w = t >> 5, lane = t & 31;
        if (w < RPB) {
            int n = 0;
            #pragma unroll
            for (int ch = 0; ch < 3; ch++) {
                bool nz = sm[OFF_SIM + (i0+w)*NN + ch*32 + lane] != 0.0f;
                n += __popc(__ballot_sync(0xffffffffu, nz));
            }
            if (lane == 0) invn_s[w] = 1.0f / fmaxf((float)n, 1.0f);
        }
    }
    // ---- 3. own sim rows transposed: r0T[j][rr]  (RPB*NN = 384 > THREADS!) ----
    for (int idx = t; idx < RPB*NN; idx += THREADS) {
        int rr = idx / NN, j = idx - rr*NN;
        sm[OFF_R0T + j*RPB + rr] = sm[OFF_SIM + (i0+rr)*NN + j];
    }
    __syncthreads();

    // ---- 4. hop1: 192 threads = 96 cols x 2 j-halves; combine via HOPP ----
    {
        float a0=0.f,a1=0.f,a2=0.f,a3=0.f;
        int jh = 0, col = 0;
        if (t < 2*NN) {
            jh = (t >= NN); col = t - NN*jh;
            int jb = jh*48;
            #pragma unroll 8
            for (int j = jb; j < jb+48; j++) {
                float  sv = sm[OFF_SIM + j*NN + col];
                float4 rv = *(const float4*)&sm[OFF_R0T + j*RPB];
                a0 = fmaf(rv.x, sv, a0); a1 = fmaf(rv.y, sv, a1);
                a2 = fmaf(rv.z, sv, a2); a3 = fmaf(rv.w, sv, a3);
            }
            if (jh) *(float4*)&sm[OFF_HOPP + col*RPB] = make_float4(a0,a1,a2,a3);
        }
        __syncthreads();
        if (t < 2*NN && !jh) {
            float4 p = *(const float4*)&sm[OFF_HOPP + col*RPB];
            *(float4*)&sm[OFF_R1T + col*RPB] =
                make_float4((a0+p.x)*invn_s[0], (a1+p.y)*invn_s[1],
                            (a2+p.z)*invn_s[2], (a3+p.w)*invn_s[3]);
        }
    }
    __syncthreads();

    // ---- 5. hop2 ----
    {
        float a0=0.f,a1=0.f,a2=0.f,a3=0.f;
        int jh = 0, col = 0;
        if (t < 2*NN) {
            jh = (t >= NN); col = t - NN*jh;
            int jb = jh*48;
            #pragma unroll 8
            for (int j = jb; j < jb+48; j++) {
                float  sv = sm[OFF_SIM + j*NN + col];
                float4 rv = *(const float4*)&sm[OFF_R1T + j*RPB];
                a0 = fmaf(rv.x, sv, a0); a1 = fmaf(rv.y, sv, a1);
                a2 = fmaf(rv.z, sv, a2); a3 = fmaf(rv.w, sv, a3);
            }
            if (jh) *(float4*)&sm[OFF_HOPP + col*RPB] = make_float4(a0,a1,a2,a3);
        }
        __syncthreads();
        if (t < 2*NN && !jh) {
            float4 p = *(const float4*)&sm[OFF_HOPP + col*RPB];
            *(float4*)&sm[OFF_R2T + col*RPB] =
                make_float4((a0+p.x)*invn_s[0], (a1+p.y)*invn_s[1],
                            (a2+p.z)*invn_s[2], (a3+p.w)*invn_s[3]);
        }
    }
    __syncthreads();   // sim tile dead from here; pack/part overlay it

    // ---- 6. compaction (warps 0..3 -> own row), reads r0T not sim ----
    {
        int w = t >> 5, lane = t & 31;
        if (w < RPB) {
            float4* pk = (float4*)&sm[OFF_PACK];
            int cnt = 0; float cs = 0.0f;
            #pragma unroll
            for (int ch = 0; ch < 3; ch++) {
                int   j  = ch*32 + lane;
                float s0 = sm[OFF_R0T + j*RPB + w];
                float rv = r[bbase + (size_t)(i0+w)*NN + j];
                float c  = 0.0f;
                if (rv < 5.0f && s0 != 0.0f)
                    c = 0.5f * (__cosf(rv * PI_5) + 1.0f);
                cs += c;
                bool p = (c != 0.0f);
                unsigned bm = __ballot_sync(0xffffffffu, p);
                int pos = cnt + __popc(bm & ((1u << lane) - 1u));
                if (p)
                    pk[w*NN + pos] = make_float4(s0, sm[OFF_R1T + j*RPB + w],
                                                 sm[OFF_R2T + j*RPB + w], c * LN2f);
                cnt += __popc(bm);
            }
            #pragma unroll
            for (int o = 16; o > 0; o >>= 1) cs += __shfl_down_sync(0xffffffffu, cs, o);
            if (lane == 0) { cnt_s[w] = cnt; csum_s[w] = cs; }
        }
    }
    __syncthreads();

    // ---- 7. accS (log2 domain), j-loop split across two halves ----
    {
        int f = t & (FF-1), h = t >> 7;        // h in {0,1}
        float w0 = fw1[f]        * LOG2Ef;
        float w1 = fw1[FF + f]   * LOG2Ef;
        float w2 = fw1[2*FF + f] * LOG2Ef;
        float b1 = fb1[f]        * LOG2Ef;
        const float4* pk = (const float4*)&sm[OFF_PACK];
        float accv[RPB];
        #pragma unroll
        for (int rr = 0; rr < RPB; rr++) {
            int cnt  = cnt_s[rr];
            int half = (cnt + 1) >> 1;
            int jb   = h ? half : 0;
            int je   = h ? cnt  : half;
            float a = 0.0f;
            for (int jj = jb; jj < je; jj++) {
                float4 p  = pk[rr*NN + jj];
                float  tt = fmaf(p.z, w2, fmaf(p.y, w1, fmaf(p.x, w0, b1)));
                float  u;  asm("ex2.approx.f32 %0, %1;" : "=f"(u)  : "f"(-fabsf(tt)));
                float  v  = fmaf(u, 0.5f, 0.5f);
                float  lg; asm("lg2.approx.f32 %0, %1;" : "=f"(lg) : "f"(v));
                a = fmaf(p.w, fmaxf(tt, 0.0f) + lg, a);
            }
            accv[rr] = a;
        }
        if (h) {
            #pragma unroll
            for (int rr = 0; rr < RPB; rr++) sm[OFF_SPART + rr*FF + f] = accv[rr];
        }
        __syncthreads();
        if (!h) {
            #pragma unroll
            for (int rr = 0; rr < RPB; rr++)
                sm[OFF_SA + rr*FF + f] = accv[rr] + sm[OFF_SPART + rr*FF + f];
        }
    }
    // SA writes are ordered before GEMM2's reads by the syncs inside the GEMM chain;
    // GEMM1 touches only sX/PART which are disjoint from SA/SPART/PACK.

    // ---- 8. GEMM chain: 8-way k-split, weights via LDG, partials in smem ----
    const int orow = t >> 5;          // reducer row (t<128: 0..3)
    const int oc   = (t & 31) * 4;    // reducer cols

    // GEMM1: ypre = x @ Win   (result stays in reducer registers, t<128)
    gemm_partial(Win, &sm[OFF_SX], &sm[OFF_PART], t);
    __syncthreads();
    float4 yp = make_float4(0.f,0.f,0.f,0.f);
    if (t < 128) yp = gemm_reduce(&sm[OFF_PART], orow, oc);
    __syncthreads();                               // part reads done

    // GEMM2: t2 = (A @ fw2 + fb2*csum) * ypre  -> sX (x is dead)
    gemm_partial(fw2, &sm[OFF_SA], &sm[OFF_PART], t);
    __syncthreads();
    if (t < 128) {
        float4 t2 = gemm_reduce(&sm[OFF_PART], orow, oc);
        float  cs = csum_s[orow];
        float4 fb = *(const float4*)&fb2[oc];
        float4 o;
        o.x = fmaf(fb.x, cs, t2.x) * yp.x;  o.y = fmaf(fb.y, cs, t2.y) * yp.y;
        o.z = fmaf(fb.z, cs, t2.z) * yp.z;  o.w = fmaf(fb.w, cs, t2.w) * yp.w;
        *(float4*)&sm[OFF_SX + orow*FF + oc] = o;
    }
    __syncthreads();                               // sX visible, part reads done

    // GEMM3: out = ssp(t2 @ Wout + bout)
    gemm_partial(Wout, &sm[OFF_SX], &sm[OFF_PART], t);
    __syncthreads();
    if (t < 128) {
        float4 t3 = gemm_reduce(&sm[OFF_PART], orow, oc);
        float4 bo = *(const float4*)&bout[oc];
        float  vin[4] = { t3.x + bo.x, t3.y + bo.y, t3.z + bo.z, t3.w + bo.w };
        float4 o; float* op = (float*)&o;
        #pragma unroll
        for (int q = 0; q < 4; q++) {
            float u = vin[q] * LOG2Ef;
            float e;  asm("ex2.approx.f32 %0, %1;" : "=f"(e)  : "f"(-fabsf(u)));
            float v = fmaf(e, 0.5f, 0.5f);
            float lg; asm("lg2.approx.f32 %0, %1;" : "=f"(lg) : "f"(v));
            op[q] = LN2f * (fmaxf(u, 0.0f) + lg);
        }
        *(float4*)&out[(size_t)(b*NN + i0 + orow)*FF + oc] = o;
    }
}

// ================= launch =================
extern "C" void kernel_launch(void* const* d_in, const int* in_sizes, int n_in,
                              void* d_out, int out_size) {
    const float* x      = (const float*)d_in[0];
    const float* r      = (const float*)d_in[1];
    // d_in[2] = neighbors (unused by this forward variant)
    const float* mask   = (const float*)d_in[3];
    const float* W_in2f = (const float*)d_in[4];
    const float* fw1    = (const float*)d_in[5];
    const float* fb1    = (const float*)d_in[6];
    const float* fw2    = (const float*)d_in[7];
    const float* fb2    = (const float*)d_in[8];
    const float* W_out  = (const float*)d_in[9];
    const float* b_out  = (const float*)d_in[10];
    float* out = (float*)d_out;

    // Unconditional (no static guard): idempotent, immediate host API,
    // identical behavior on every call including the graph-capture call.
    cudaFuncSetAttribute(k_fused, cudaFuncAttributeMaxDynamicSharedMemorySize, SMEM_BYTES);

    k_fused<<<NBLK, THREADS, SMEM_BYTES>>>(x, r, mask, W_in2f, fw1, fb1, fw2, fb2,
                                           W_out, b_out, out);
}